// round 6
// baseline (speedup 1.0000x reference)
#include <cuda_runtime.h>
#include <cuda_fp16.h>
#include <cstdint>

// ---------------------------------------------------------------------------
// y = sum_b ((x*v2_b) @ sign(V_b)^T * (v1_b*u2_b)) @ sign(U_b)^T * u1_b + bias
// M=8192, IN=4096, SPLIT=1024, OUT=4096, 2 branches.
// fp16 operands (signs exact, u1 folded into Wu, v2 into x), two HMMA GEMMs:
// G1 per branch -> Hcat[8192,2048] fp16 scaled by s1; G2 (K=2048) -> fp32+bias.
// R5: warp tile 64x64 (4 warps, 128 thr, 2 CTAs/SM), grid (Ntiles, Mtiles)
// for L2 reuse of B, 4-stage cp.async ring, 80B-padded conflict-free LDSM.
// ---------------------------------------------------------------------------

#define BM 128
#define BN 128
#define BK 32
#define STG 4
#define ROWB 80                 // padded row stride in bytes (40 halfs)
#define TILEB (BM*ROWB)         // 10240
#define STGB (2*TILEB)          // 20480
#define SMEMB (STG*STGB)        // 81920

__device__ __align__(16) __half g_xs[2ull*8192*4096];
__device__ __align__(16) __half g_wv[2ull*1024*4096];
__device__ __align__(16) __half g_wu[4096ull*2048];
__device__ __align__(16) __half g_h [8192ull*2048];
__device__ float g_s1[2048];

__device__ __forceinline__ uint32_t smem_u32(const void* p){
  uint32_t a;
  asm("{ .reg .u64 t; cvta.to.shared.u64 t, %1; cvt.u32.u64 %0, t; }" : "=r"(a) : "l"(p));
  return a;
}
__device__ __forceinline__ void cp16(uint32_t dst, const void* src){
  asm volatile("cp.async.cg.shared.global [%0], [%1], 16;" :: "r"(dst), "l"(src));
}
__device__ __forceinline__ void ldsm4(uint32_t& r0, uint32_t& r1, uint32_t& r2,
                                      uint32_t& r3, uint32_t addr){
  asm volatile("ldmatrix.sync.aligned.m8n8.x4.shared.b16 {%0,%1,%2,%3}, [%4];"
    : "=r"(r0), "=r"(r1), "=r"(r2), "=r"(r3) : "r"(addr));
}
__device__ __forceinline__ void mma16816(float* d, const uint32_t* a, const uint32_t* b){
  asm volatile("mma.sync.aligned.m16n8k16.row.col.f32.f16.f16.f32 "
    "{%0,%1,%2,%3}, {%4,%5,%6,%7}, {%8,%9}, {%0,%1,%2,%3};"
    : "+f"(d[0]), "+f"(d[1]), "+f"(d[2]), "+f"(d[3])
    : "r"(a[0]), "r"(a[1]), "r"(a[2]), "r"(a[3]), "r"(b[0]), "r"(b[1]));
}
__device__ __forceinline__ float sg(float v){ return v > 0.f ? 1.f : (v < 0.f ? -1.f : 0.f); }
__device__ __forceinline__ uint2 pack4(float a, float b, float c, float d){
  __half2 h0 = __floats2half2_rn(a, b), h1 = __floats2half2_rn(c, d);
  uint2 o;
  o.x = *reinterpret_cast<uint32_t*>(&h0);
  o.y = *reinterpret_cast<uint32_t*>(&h1);
  return o;
}

// ------------------------------- prep kernels -------------------------------
__global__ void prep_x_k(const float4* __restrict__ x, const float* __restrict__ v2,
                         const float* __restrict__ v2R){
  uint2* oA = reinterpret_cast<uint2*>(g_xs);
  uint2* oB = reinterpret_cast<uint2*>(g_xs + 8192ull*4096);
  const size_t n = 8388608ull; // 8192*4096/4
  for (size_t i = blockIdx.x*(size_t)blockDim.x + threadIdx.x; i < n;
       i += (size_t)gridDim.x*blockDim.x){
    float4 xv = x[i];
    int k = (int)(i & 1023) * 4;
    float4 a = *(const float4*)(v2 + k);
    float4 b = *(const float4*)(v2R + k);
    oA[i] = pack4(xv.x*a.x, xv.y*a.y, xv.z*a.z, xv.w*a.w);
    oB[i] = pack4(xv.x*b.x, xv.y*b.y, xv.z*b.z, xv.w*b.w);
  }
}

__global__ void prep_wv_k(const float4* __restrict__ V, const float4* __restrict__ VR){
  uint2* oA = reinterpret_cast<uint2*>(g_wv);
  uint2* oB = reinterpret_cast<uint2*>(g_wv + 1024ull*4096);
  const size_t n = 1048576ull; // 1024*4096/4
  for (size_t i = blockIdx.x*(size_t)blockDim.x + threadIdx.x; i < n;
       i += (size_t)gridDim.x*blockDim.x){
    float4 v = V[i];
    oA[i] = pack4(sg(v.x), sg(v.y), sg(v.z), sg(v.w));
    float4 r = VR[i];
    oB[i] = pack4(sg(r.x), sg(r.y), sg(r.z), sg(r.w));
  }
}

__global__ void prep_wu_k(const float4* __restrict__ U, const float4* __restrict__ UR,
                          const float* __restrict__ u1, const float* __restrict__ u1R){
  uint2* o = reinterpret_cast<uint2*>(g_wu);
  const size_t n = 1048576ull; // 4096*1024/4
  for (size_t i = blockIdx.x*(size_t)blockDim.x + threadIdx.x; i < n;
       i += (size_t)gridDim.x*blockDim.x){
    int orow = (int)(i >> 8), j4 = (int)(i & 255);
    float s  = u1[orow], sR = u1R[orow];
    float4 u = U[i];
    o[(size_t)orow*512 + j4]       = pack4(sg(u.x)*s,  sg(u.y)*s,  sg(u.z)*s,  sg(u.w)*s);
    float4 r = UR[i];
    o[(size_t)orow*512 + 256 + j4] = pack4(sg(r.x)*sR, sg(r.y)*sR, sg(r.z)*sR, sg(r.w)*sR);
  }
}

__global__ void prep_s1_k(const float* v1, const float* u2,
                          const float* v1R, const float* u2R){
  int j = blockIdx.x*blockDim.x + threadIdx.x;
  if (j < 1024){ g_s1[j] = v1[j]*u2[j]; g_s1[1024+j] = v1R[j]*u2R[j]; }
}

// -------------------------------- GEMM --------------------------------------
// D[M,N] = A[M,K] @ B[N,K]^T, fp16 in, fp32 accum. 128 threads, 4 warps (2x2),
// warp tile 64x64. grid = (N-tiles, M-tiles, branch) so a wave shares B in L2.
// MODE 0: outH[row*2048 + bz*1024 + col] = half(acc * aux[bz*1024+col])
// MODE 1: outF[row*4096 + col] = acc + aux[col]
template<int MODE>
__global__ void __launch_bounds__(128, 2)
gemm_k(const __half* __restrict__ A, const __half* __restrict__ B, int K,
       size_t strideA, size_t strideB, const float* __restrict__ aux,
       __half* __restrict__ outH, float* __restrict__ outF)
{
  extern __shared__ char smem[];
  const uint32_t sb = smem_u32(smem);
  const int tid = threadIdx.x, wid = tid >> 5, lane = tid & 31;
  const int ntile = blockIdx.x, mtile = blockIdx.y, bz = blockIdx.z;
  const int wrow = wid >> 1, wcol = wid & 1;

  const __half* Ab = A + strideA*bz + (size_t)mtile*BM*K;
  const __half* Bb = B + strideB*bz + (size_t)ntile*BN*K;
  const int KS = K / BK;

  // 8 x 16B chunks per thread per stage (A: 512 chunks, B: 512 chunks)
  #define LOAD_STAGE(buf, ks_) do {                                          \
    uint32_t as_ = sb + (buf)*STGB, bs_ = as_ + TILEB;                       \
    int k0_ = (ks_)*BK;                                                      \
    _Pragma("unroll")                                                        \
    for (int i_ = 0; i_ < 4; i_++){                                          \
      int idx_ = tid + i_*128;                                               \
      int r_ = idx_ >> 2, ch_ = idx_ & 3;                                    \
      cp16(as_ + r_*ROWB + ch_*16, Ab + (size_t)r_*K + k0_ + ch_*8);         \
      cp16(bs_ + r_*ROWB + ch_*16, Bb + (size_t)r_*K + k0_ + ch_*8);         \
    }                                                                        \
    asm volatile("cp.async.commit_group;" ::: "memory");                     \
  } while(0)

  LOAD_STAGE(0, 0);
  LOAD_STAGE(1, 1);
  LOAD_STAGE(2, 2);

  float acc[4][8][4];
  #pragma unroll
  for (int i = 0; i < 4; i++)
    #pragma unroll
    for (int j = 0; j < 8; j++)
      #pragma unroll
      for (int k = 0; k < 4; k++) acc[i][j][k] = 0.f;

  // per-lane ldmatrix base (lane&15 = row within 16, lane>>4 = 8-col half)
  const uint32_t aBase = (uint32_t)((wrow*64 + (lane & 15))*ROWB + (lane >> 4)*16);
  const uint32_t bBase = (uint32_t)((wcol*64 + (lane & 15))*ROWB + (lane >> 4)*16);

  for (int ks = 0; ks < KS; ks++){
    asm volatile("cp.async.wait_group %0;" :: "n"(STG-2) : "memory");
    __syncthreads();
    if (ks + STG - 1 < KS){
      LOAD_STAGE((ks + STG - 1) & (STG - 1), ks + STG - 1);
    } else {
      asm volatile("cp.async.commit_group;" ::: "memory");  // uniform accounting
    }

    const uint32_t as = sb + (ks & (STG-1))*STGB;
    const uint32_t bs = as + TILEB;

    uint32_t ar[4][2][4], br[8][2][2];
    #pragma unroll
    for (int kf = 0; kf < 2; kf++){
      #pragma unroll
      for (int mf = 0; mf < 4; mf++)
        ldsm4(ar[mf][kf][0], ar[mf][kf][1], ar[mf][kf][2], ar[mf][kf][3],
              as + aBase + mf*(16*ROWB) + kf*32);
      #pragma unroll
      for (int nf2 = 0; nf2 < 4; nf2++){
        uint32_t t0, t1, t2, t3;
        ldsm4(t0, t1, t2, t3, bs + bBase + nf2*(16*ROWB) + kf*32);
        br[nf2*2+0][kf][0] = t0; br[nf2*2+1][kf][0] = t1;
        br[nf2*2+0][kf][1] = t2; br[nf2*2+1][kf][1] = t3;
      }
    }
    #pragma unroll
    for (int kf = 0; kf < 2; kf++)
      #pragma unroll
      for (int mf = 0; mf < 4; mf++)
        #pragma unroll
        for (int nf = 0; nf < 8; nf++)
          mma16816(acc[mf][nf], ar[mf][kf], br[nf][kf]);
  }

  // ----------------------------- epilogue -----------------------------------
  const int row0 = mtile*BM + wrow*64 + (lane >> 2);
  const int col0 = ntile*BN + wcol*64 + (lane & 3)*2;

  if (MODE == 0){
    #pragma unroll
    for (int mf = 0; mf < 4; mf++)
      #pragma unroll
      for (int nf = 0; nf < 8; nf++){
        size_t gc = (size_t)bz*1024 + col0 + nf*8;
        float2 s = *(const float2*)(aux + gc);
        int r = row0 + mf*16;
        __half2 lo = __floats2half2_rn(acc[mf][nf][0]*s.x, acc[mf][nf][1]*s.y);
        __half2 hi = __floats2half2_rn(acc[mf][nf][2]*s.x, acc[mf][nf][3]*s.y);
        *reinterpret_cast<__half2*>(outH + (size_t)r*2048 + gc) = lo;
        *reinterpret_cast<__half2*>(outH + (size_t)(r+8)*2048 + gc) = hi;
      }
  } else {
    #pragma unroll
    for (int mf = 0; mf < 4; mf++)
      #pragma unroll
      for (int nf = 0; nf < 8; nf++){
        int c = col0 + nf*8;
        float2 b2 = *(const float2*)(aux + c);
        int r = row0 + mf*16;
        float2 lo = make_float2(acc[mf][nf][0] + b2.x, acc[mf][nf][1] + b2.y);
        float2 hi = make_float2(acc[mf][nf][2] + b2.x, acc[mf][nf][3] + b2.y);
        *reinterpret_cast<float2*>(outF + (size_t)r*4096 + c) = lo;
        *reinterpret_cast<float2*>(outF + (size_t)(r+8)*4096 + c) = hi;
      }
  }
  #undef LOAD_STAGE
}

// ----------------------------- launch ---------------------------------------
extern "C" void kernel_launch(void* const* d_in, const int* in_sizes, int n_in,
                              void* d_out, int out_size){
  (void)in_sizes; (void)n_in; (void)out_size;
  const float* x    = (const float*)d_in[0];
  const float* V    = (const float*)d_in[1];
  const float* U    = (const float*)d_in[2];
  const float* v2   = (const float*)d_in[3];
  const float* v1   = (const float*)d_in[4];
  const float* u2   = (const float*)d_in[5];
  const float* u1   = (const float*)d_in[6];
  const float* V_R  = (const float*)d_in[7];
  const float* U_R  = (const float*)d_in[8];
  const float* v2_R = (const float*)d_in[9];
  const float* v1_R = (const float*)d_in[10];
  const float* u2_R = (const float*)d_in[11];
  const float* u1_R = (const float*)d_in[12];
  const float* bias = (const float*)d_in[13];
  float* out = (float*)d_out;

  __half *xs, *wv, *wu, *h; float* s1;
  cudaGetSymbolAddress((void**)&xs, g_xs);
  cudaGetSymbolAddress((void**)&wv, g_wv);
  cudaGetSymbolAddress((void**)&wu, g_wu);
  cudaGetSymbolAddress((void**)&h,  g_h);
  cudaGetSymbolAddress((void**)&s1, g_s1);

  prep_x_k <<<4096, 256>>>((const float4*)x, v2, v2_R);
  prep_wv_k<<<1024, 256>>>((const float4*)V, (const float4*)V_R);
  prep_wu_k<<<1024, 256>>>((const float4*)U, (const float4*)U_R, u1, u1_R);
  prep_s1_k<<<4, 256>>>(v1, u2, v1_R, u2_R);

  cudaFuncSetAttribute(gemm_k<0>, cudaFuncAttributeMaxDynamicSharedMemorySize, SMEMB);
  cudaFuncSetAttribute(gemm_k<1>, cudaFuncAttributeMaxDynamicSharedMemorySize, SMEMB);

  dim3 g1(8, 64, 2);   // N-tiles(1024/128) x M-tiles x branch
  gemm_k<0><<<g1, 128, SMEMB>>>(xs, wv, 4096, 8192ull*4096, 1024ull*4096,
                                s1, h, nullptr);
  dim3 g2(32, 64, 1);  // N-tiles(4096/128) x M-tiles
  gemm_k<1><<<g2, 128, SMEMB>>>(h, wu, 2048, 0, 0, bias, nullptr, out);
}

// round 7
// speedup vs baseline: 1.3615x; 1.3615x over previous
#include <cuda_runtime.h>
#include <cuda_fp16.h>
#include <cstdint>

// ---------------------------------------------------------------------------
// y = sum_b ((x*v2_b) @ sign(V_b)^T * (v1_b*u2_b)) @ sign(U_b)^T * u1_b + bias
// Binary +-1 weights -> exact 2:4 sparsity:
//   pair (w0,w1): a=(w0+w1)/2, b=(w0-w1)/2; exactly one is +-1 (= w0).
//   x0w0+x1w1 = a*(x0+x1) + b*(x0-x1).
// x' stores (p,m)=(xs0+xs1, xs0-xs1) pairs; W' compressed value = sgn(W[:,2t]),
// metadata index from sgn(w0)==sgn(w1). mma.sp::ordered_metadata.m16n8k32
// halves tensor-instruction count vs dense HMMA (which is pipe-bound).
// Sparse operand = weights (mma M-dim), batch = B operand -> output transposed,
// fixed via smem-transpose epilogue. GEMM1 epilogue fuses s1 scale + pair
// transform (shfl_xor 4) so GEMM2 reads H' directly.
// ---------------------------------------------------------------------------

#define WT 128      // weight rows per CTA
#define XT 128      // batch cols per CTA
#define BKL 64      // logical K per stage
#define STG 3
#define AROWB 80    // compressed A row: 32 halfs (64B) padded to 80
#define BROWB 144   // B row: 64 halfs (128B) padded to 144
#define SPA (WT*AROWB)            // 10240
#define SPB (XT*BROWB)            // 18432
#define SPM 1024                  // meta: 8 b16 x 2 chunks x 16 words x 4B
#define STGB (SPA+SPB+SPM)        // 29696
#define SMEMB (STG*STGB)          // 89088

__device__ __align__(16) __half   g_xp[2ull*8192*4096];   // x' pairs per branch
__device__ __align__(16) __half   g_cv[2ull*1024*2048];   // compressed sgn(V)
__device__ __align__(16) __half   g_cu[4096ull*1024];     // compressed sgn(U)*u1 (concat)
__device__ __align__(16) __half   g_hp[8192ull*2048];     // H' pairs
__device__ __align__(16) uint32_t g_mv[2ull*64*128*16];   // metadata V
__device__ __align__(16) uint32_t g_mu[256ull*64*16];     // metadata Ucat
__device__ float g_s1[2048];

__device__ __forceinline__ uint32_t smem_u32(const void* p){
  uint32_t a;
  asm("{ .reg .u64 t; cvta.to.shared.u64 t, %1; cvt.u32.u64 %0, t; }" : "=r"(a) : "l"(p));
  return a;
}
__device__ __forceinline__ void cp16(uint32_t dst, const void* src){
  asm volatile("cp.async.cg.shared.global [%0], [%1], 16;" :: "r"(dst), "l"(src));
}
__device__ __forceinline__ void cp8(uint32_t dst, const void* src){
  asm volatile("cp.async.ca.shared.global [%0], [%1], 8;" :: "r"(dst), "l"(src));
}
__device__ __forceinline__ void ldsm4(uint32_t& r0, uint32_t& r1, uint32_t& r2,
                                      uint32_t& r3, uint32_t addr){
  asm volatile("ldmatrix.sync.aligned.m8n8.x4.shared.b16 {%0,%1,%2,%3}, [%4];"
    : "=r"(r0), "=r"(r1), "=r"(r2), "=r"(r3) : "r"(addr));
}
__device__ __forceinline__ void mma_sp(float* d, const uint32_t* a,
                                       const uint32_t* b, uint32_t e){
  asm volatile("mma.sp::ordered_metadata.sync.aligned.m16n8k32.row.col.f32.f16.f16.f32 "
    "{%0,%1,%2,%3}, {%4,%5,%6,%7}, {%8,%9,%10,%11}, {%0,%1,%2,%3}, %12, 0x0;"
    : "+f"(d[0]), "+f"(d[1]), "+f"(d[2]), "+f"(d[3])
    : "r"(a[0]), "r"(a[1]), "r"(a[2]), "r"(a[3]),
      "r"(b[0]), "r"(b[1]), "r"(b[2]), "r"(b[3]), "r"(e));
}
__device__ __forceinline__ float sg(float v){ return v > 0.f ? 1.f : (v < 0.f ? -1.f : 0.f); }

// ------------------------------- prep kernels -------------------------------
// x' pairs: xp[br][m][2t] = xs[2t]+xs[2t+1], xp[..][2t+1] = xs[2t]-xs[2t+1]
__global__ void prep_xp_k(const float2* __restrict__ x, const float2* __restrict__ v2,
                          const float2* __restrict__ v2R){
  uint32_t* oA = reinterpret_cast<uint32_t*>(g_xp);
  uint32_t* oB = reinterpret_cast<uint32_t*>(g_xp + 8192ull*4096);
  const size_t n = 8192ull*2048;
  for (size_t i = blockIdx.x*(size_t)blockDim.x + threadIdx.x; i < n;
       i += (size_t)gridDim.x*blockDim.x){
    float2 xv = x[i];
    int t = (int)(i & 2047);
    float2 a = v2[t], b = v2R[t];
    float s0 = xv.x*a.x, s1 = xv.y*a.y;
    __half2 hA = __floats2half2_rn(s0 + s1, s0 - s1);
    oA[i] = *reinterpret_cast<uint32_t*>(&hA);
    float r0 = xv.x*b.x, r1 = xv.y*b.y;
    __half2 hB = __floats2half2_rn(r0 + r1, r0 - r1);
    oB[i] = *reinterpret_cast<uint32_t*>(&hB);
  }
}

// compressed V: cv[br][j][t] = sgn(V[j][2t])  (fp16 +-1)
__global__ void prep_cv_k(const float4* __restrict__ V, const float4* __restrict__ VR){
  uint2* oA = reinterpret_cast<uint2*>(g_cv);
  uint2* oB = reinterpret_cast<uint2*>(g_cv + 1024ull*2048);
  const size_t n = 1024ull*512;          // rows x (2048 t / 4)
  for (size_t i = blockIdx.x*(size_t)blockDim.x + threadIdx.x; i < n;
       i += (size_t)gridDim.x*blockDim.x){
    float4 f0 = V[i*2], f1 = V[i*2+1];
    __half2 h0 = __floats2half2_rn(sg(f0.x), sg(f0.z));
    __half2 h1 = __floats2half2_rn(sg(f1.x), sg(f1.z));
    uint2 o; o.x = *reinterpret_cast<uint32_t*>(&h0); o.y = *reinterpret_cast<uint32_t*>(&h1);
    oA[i] = o;
    f0 = VR[i*2]; f1 = VR[i*2+1];
    h0 = __floats2half2_rn(sg(f0.x), sg(f0.z));
    h1 = __floats2half2_rn(sg(f1.x), sg(f1.z));
    o.x = *reinterpret_cast<uint32_t*>(&h0); o.y = *reinterpret_cast<uint32_t*>(&h1);
    oB[i] = o;
  }
}

// compressed Ucat: cu[n][t] = sgn(Ucat[n][2t]) * u1cat[n];  t<512 from U, else U_R
__global__ void prep_cu_k(const float4* __restrict__ U, const float4* __restrict__ UR,
                          const float* __restrict__ u1, const float* __restrict__ u1R){
  uint2* o = reinterpret_cast<uint2*>(g_cu);
  const size_t n = 4096ull*256;          // rows x (1024 t / 4)
  for (size_t i = blockIdx.x*(size_t)blockDim.x + threadIdx.x; i < n;
       i += (size_t)gridDim.x*blockDim.x){
    int nr = (int)(i >> 8), g = (int)(i & 255);
    const float4* src; float sc;
    size_t base;
    if (g < 128){ src = U;  sc = u1[nr];  base = (size_t)nr*256 + g*2; }
    else        { src = UR; sc = u1R[nr]; base = (size_t)nr*256 + (g-128)*2; }
    float4 f0 = src[base], f1 = src[base+1];
    __half2 h0 = __floats2half2_rn(sg(f0.x)*sc, sg(f0.z)*sc);
    __half2 h1 = __floats2half2_rn(sg(f1.x)*sc, sg(f1.z)*sc);
    uint2 w; w.x = *reinterpret_cast<uint32_t*>(&h0); w.y = *reinterpret_cast<uint32_t*>(&h1);
    o[i] = w;
  }
}

// metadata: out[b16][K/32][16] u32. word w: q=w>>1 (quad), s=w&1 (k16 half).
// E = low16: row b16*16+q, high16: row +8. nibble g (bits 4g..): pairs 2g,2g+1:
// idx0 = eq?0:1, idx1 = eq?2:3. eq = sgn(w0)==sgn(w1). Row source split at splitK
// (row stride of each source matrix == splitK for both V and Ucat cases).
__global__ void prep_meta_k(const float* __restrict__ W0, const float* __restrict__ W1,
                            int splitK, int Korig, int rows16, uint32_t* __restrict__ out){
  const int chunks = Korig >> 5;
  const size_t n = (size_t)rows16 * chunks * 16;
  for (size_t idx = blockIdx.x*(size_t)blockDim.x + threadIdx.x; idx < n;
       idx += (size_t)gridDim.x*blockDim.x){
    int w = (int)(idx & 15);
    int q = w >> 1, s = w & 1;
    size_t cw = idx >> 4;
    int c = (int)(cw % chunks);
    int b = (int)(cw / chunks);
    int r0 = b*16 + q;
    int kb = c*32 + s*16;
    const float* W = (kb < splitK) ? W0 : W1;
    int coff = (kb < splitK) ? kb : kb - splitK;
    const float* p0 = W + (size_t)r0*splitK + coff;
    const float* p1 = p0 + (size_t)8*splitK;
    uint32_t lo = 0, hi = 0;
    #pragma unroll
    for (int g = 0; g < 4; g++){
      float4 a = *(const float4*)(p0 + g*4);
      float4 bb = *(const float4*)(p1 + g*4);
      uint32_t n0 = (((a.x < 0.f) == (a.y < 0.f)) ? 0u : 1u)
                  | ((((a.z < 0.f) == (a.w < 0.f)) ? 2u : 3u) << 2);
      uint32_t n1 = (((bb.x < 0.f) == (bb.y < 0.f)) ? 0u : 1u)
                  | ((((bb.z < 0.f) == (bb.w < 0.f)) ? 2u : 3u) << 2);
      lo |= n0 << (4*g);
      hi |= n1 << (4*g);
    }
    out[idx] = lo | (hi << 16);
  }
}

__global__ void prep_s1_k(const float* v1, const float* u2,
                          const float* v1R, const float* u2R){
  int j = blockIdx.x*blockDim.x + threadIdx.x;
  if (j < 1024){ g_s1[j] = v1[j]*u2[j]; g_s1[1024+j] = v1R[j]*u2R[j]; }
}

// --------------------------- sparse GEMM kernel -----------------------------
// D[w, b] = Wsp[w, Klog] (2:4) @ X'[b, Klog]^T. Output is weight-major in regs;
// epilogue transposes via smem. MODE 0: H' = pairTransform(D * s1) fp16.
// MODE 1: out[b][w] = D + bias[w] fp32.
template<int MODE>
__global__ void __launch_bounds__(128, 2)
spgemm_k(const __half* __restrict__ Ac, const uint32_t* __restrict__ Mt,
         const __half* __restrict__ Bx, int Klog,
         size_t strideAc, size_t strideMt, size_t strideBx,
         const float* __restrict__ aux, __half* __restrict__ outH,
         float* __restrict__ outF)
{
  extern __shared__ char smem[];
  const uint32_t sb = smem_u32(smem);
  const int tid = threadIdx.x, wid = tid >> 5, lane = tid & 31;
  const int wt = blockIdx.x, bt = blockIdx.y, bz = blockIdx.z;
  const int ww = wid >> 1, wb = wid & 1;   // warp covers weights ww*64.., batch wb*64..

  const int Kc = Klog >> 1;                // compressed halfs per weight row
  const int chunks = Klog >> 5;
  const __half* Acb = Ac + strideAc*bz + (size_t)wt*WT*Kc;
  const uint32_t* Mtb = Mt + strideMt*bz + (size_t)(wt*8)*chunks*16;
  const __half* Bxb = Bx + strideBx*bz + (size_t)bt*XT*Klog;
  const int KS = Klog / BKL;

  #define LOAD_STAGE(buf, ks_) do {                                           \
    uint32_t st_ = sb + (buf)*STGB;                                           \
    uint32_t as_ = st_, bs_ = st_ + SPA, ms_ = st_ + SPA + SPB;               \
    _Pragma("unroll")                                                         \
    for (int i_ = 0; i_ < 4; i_++){                                           \
      int idx_ = tid + i_*128, r_ = idx_ >> 2, c_ = idx_ & 3;                 \
      cp16(as_ + r_*AROWB + c_*16, Acb + (size_t)r_*Kc + (ks_)*32 + c_*8);    \
    }                                                                         \
    _Pragma("unroll")                                                         \
    for (int i_ = 0; i_ < 8; i_++){                                           \
      int idx_ = tid + i_*128, r_ = idx_ >> 3, c_ = idx_ & 7;                 \
      cp16(bs_ + r_*BROWB + c_*16, Bxb + (size_t)r_*Klog + (ks_)*64 + c_*8);  \
    }                                                                         \
    { int f_ = tid*2, b_ = f_ >> 5, rem_ = f_ & 31;                           \
      int h_ = rem_ >> 4, w_ = rem_ & 15;                                     \
      cp8(ms_ + b_*128 + h_*64 + w_*4,                                        \
          Mtb + ((size_t)b_*chunks + 2*(ks_) + h_)*16 + w_); }                \
    asm volatile("cp.async.commit_group;" ::: "memory");                      \
  } while(0)

  LOAD_STAGE(0, 0);
  LOAD_STAGE(1, 1);

  float acc[4][8][4];
  #pragma unroll
  for (int i = 0; i < 4; i++)
    #pragma unroll
    for (int j = 0; j < 8; j++)
      #pragma unroll
      for (int k = 0; k < 4; k++) acc[i][j][k] = 0.f;

  const int l15 = lane & 15, l16 = lane >> 4;
  const uint32_t eOff = ((((lane >> 2) << 1) | (lane & 1)) << 2);
  int stage = 0;

  for (int ks = 0; ks < KS; ks++){
    asm volatile("cp.async.wait_group %0;" :: "n"(STG-2) : "memory");
    __syncthreads();
    if (ks + STG - 1 < KS){
      int nb = stage + (STG - 1); if (nb >= STG) nb -= STG;
      LOAD_STAGE(nb, ks + STG - 1);
    } else {
      asm volatile("cp.async.commit_group;" ::: "memory");
    }

    const uint32_t st = sb + stage*STGB;
    const uint32_t as = st, bs2 = st + SPA, ms = st + SPA + SPB;

    #pragma unroll
    for (int h = 0; h < 2; h++){
      uint32_t af[4][4], ev[4], bf[8][4];
      #pragma unroll
      for (int i = 0; i < 4; i++){
        ldsm4(af[i][0], af[i][1], af[i][2], af[i][3],
              as + (uint32_t)((ww*64 + i*16 + l15)*AROWB) + l16*16 + h*32);
        asm volatile("ld.shared.b32 %0, [%1];" : "=r"(ev[i])
          : "r"(ms + (uint32_t)((ww*4 + i)*128 + h*64) + eOff));
      }
      #pragma unroll
      for (int j = 0; j < 4; j++){
        #pragma unroll
        for (int kh = 0; kh < 2; kh++){
          uint32_t t0, t1, t2, t3;
          ldsm4(t0, t1, t2, t3,
                bs2 + (uint32_t)((wb*64 + j*16 + l15)*BROWB) + l16*16 + h*64 + kh*32);
          bf[j*2+0][kh*2+0] = t0; bf[j*2+0][kh*2+1] = t2;
          bf[j*2+1][kh*2+0] = t1; bf[j*2+1][kh*2+1] = t3;
        }
      }
      #pragma unroll
      for (int i = 0; i < 4; i++)
        #pragma unroll
        for (int j = 0; j < 8; j++)
          mma_sp(acc[i][j], af[i], bf[j], ev[i]);
    }
    if (++stage == STG) stage = 0;
  }

  asm volatile("cp.async.wait_group 0;" ::: "memory");
  __syncthreads();

  // ----------------------------- epilogue -----------------------------------
  const int qr = lane >> 2;            // mma row within 16 (0-7; +8 for d2,d3)
  const int qc = (lane & 3) * 2;       // mma col (batch) within 8

  if (MODE == 0){
    // scale by s1 (per weight row), pair-transform across row parity (shfl xor 4)
    const uint32_t epi = sb + wid*8448;     // 64 x (66 halfs) region
    const int jgBase = bz*1024 + wt*128 + ww*64;
    #pragma unroll
    for (int mf = 0; mf < 4; mf++){
      float sA = aux[jgBase + mf*16 + qr];
      float sB = aux[jgBase + mf*16 + qr + 8];
      #pragma unroll
      for (int nf = 0; nf < 8; nf++){
        float v0 = acc[mf][nf][0]*sA, v1 = acc[mf][nf][1]*sA;
        float v2 = acc[mf][nf][2]*sB, v3 = acc[mf][nf][3]*sB;
        float p0 = __shfl_xor_sync(0xffffffffu, v0, 4);
        float p1 = __shfl_xor_sync(0xffffffffu, v1, 4);
        float p2 = __shfl_xor_sync(0xffffffffu, v2, 4);
        float p3 = __shfl_xor_sync(0xffffffffu, v3, 4);
        bool even = (qr & 1) == 0;
        float r0 = even ? v0 + p0 : p0 - v0;
        float r1 = even ? v1 + p1 : p1 - v1;
        float r2 = even ? v2 + p2 : p2 - v2;
        float r3 = even ? v3 + p3 : p3 - v3;
        int bc = nf*8 + qc, jl = mf*16 + qr;
        __half* s0 = reinterpret_cast<__half*>(smem) + 0;  // unused; use raw asm stores
        (void)s0;
        uint32_t a0 = epi + (uint32_t)(bc*132 + jl*2);
        uint32_t a1 = epi + (uint32_t)((bc+1)*132 + jl*2);
        __half h0 = __float2half_rn(r0), h1 = __float2half_rn(r1);
        __half h2 = __float2half_rn(r2), h3 = __float2half_rn(r3);
        asm volatile("st.shared.b16 [%0], %1;" :: "r"(a0),      "h"(*(uint16_t*)&h0));
        asm volatile("st.shared.b16 [%0], %1;" :: "r"(a1),      "h"(*(uint16_t*)&h1));
        asm volatile("st.shared.b16 [%0], %1;" :: "r"(a0 + 16), "h"(*(uint16_t*)&h2));
        asm volatile("st.shared.b16 [%0], %1;" :: "r"(a1 + 16), "h"(*(uint16_t*)&h3));
      }
    }
    __syncwarp();
    const int colg = bz*1024 + wt*128 + ww*64 + lane*2;
    #pragma unroll 4
    for (int rb = 0; rb < 64; rb++){
      uint32_t v;
      asm volatile("ld.shared.b32 %0, [%1];" : "=r"(v) : "r"(epi + (uint32_t)(rb*132 + lane*4)));
      *reinterpret_cast<uint32_t*>(outH + (size_t)(bt*128 + wb*64 + rb)*2048 + colg) = v;
    }
  } else {
    const uint32_t epi = sb + wid*16896;    // 64 x (66 floats) region
    #pragma unroll
    for (int mf = 0; mf < 4; mf++){
      #pragma unroll
      for (int nf = 0; nf < 8; nf++){
        int bc = nf*8 + qc, jl = mf*16 + qr;
        uint32_t a0 = epi + (uint32_t)(bc*264 + jl*4);
        uint32_t a1 = epi + (uint32_t)((bc+1)*264 + jl*4);
        asm volatile("st.shared.f32 [%0], %1;" :: "r"(a0),      "f"(acc[mf][nf][0]));
        asm volatile("st.shared.f32 [%0], %1;" :: "r"(a1),      "f"(acc[mf][nf][1]));
        asm volatile("st.shared.f32 [%0], %1;" :: "r"(a0 + 32), "f"(acc[mf][nf][2]));
        asm volatile("st.shared.f32 [%0], %1;" :: "r"(a1 + 32), "f"(acc[mf][nf][3]));
      }
    }
    __syncwarp();
    const int c0 = wt*128 + ww*64 + lane*2;
    float2 bb = *reinterpret_cast<const float2*>(aux + c0);
    #pragma unroll 4
    for (int rb = 0; rb < 64; rb++){
      float2 v;
      asm volatile("ld.shared.v2.f32 {%0,%1}, [%2];" : "=f"(v.x), "=f"(v.y)
        : "r"(epi + (uint32_t)(rb*264 + lane*8)));
      v.x += bb.x; v.y += bb.y;
      *reinterpret_cast<float2*>(outF + (size_t)(bt*128 + wb*64 + rb)*4096 + c0) = v;
    }
  }
  #undef LOAD_STAGE
}

// ----------------------------- launch ---------------------------------------
extern "C" void kernel_launch(void* const* d_in, const int* in_sizes, int n_in,
                              void* d_out, int out_size){
  (void)in_sizes; (void)n_in; (void)out_size;
  const float* x    = (const float*)d_in[0];
  const float* V    = (const float*)d_in[1];
  const float* U    = (const float*)d_in[2];
  const float* v2   = (const float*)d_in[3];
  const float* v1   = (const float*)d_in[4];
  const float* u2   = (const float*)d_in[5];
  const float* u1   = (const float*)d_in[6];
  const float* V_R  = (const float*)d_in[7];
  const float* U_R  = (const float*)d_in[8];
  const float* v2_R = (const float*)d_in[9];
  const float* v1_R = (const float*)d_in[10];
  const float* u2_R = (const float*)d_in[11];
  const float* u1_R = (const float*)d_in[12];
  const float* bias = (const float*)d_in[13];
  float* out = (float*)d_out;

  __half *xp, *cv, *cu, *hp; uint32_t *mv, *mu; float* s1;
  cudaGetSymbolAddress((void**)&xp, g_xp);
  cudaGetSymbolAddress((void**)&cv, g_cv);
  cudaGetSymbolAddress((void**)&cu, g_cu);
  cudaGetSymbolAddress((void**)&hp, g_hp);
  cudaGetSymbolAddress((void**)&mv, g_mv);
  cudaGetSymbolAddress((void**)&mu, g_mu);
  cudaGetSymbolAddress((void**)&s1, g_s1);

  prep_xp_k<<<8192, 256>>>((const float2*)x, (const float2*)v2, (const float2*)v2_R);
  prep_cv_k<<<1024, 256>>>((const float4*)V, (const float4*)V_R);
  prep_cu_k<<<2048, 256>>>((const float4*)U, (const float4*)U_R, u1, u1_R);
  prep_meta_k<<<512, 256>>>(V,   nullptr, 4096, 4096, 64,  mv);
  prep_meta_k<<<512, 256>>>(V_R, nullptr, 4096, 4096, 64,  mv + 64ull*128*16);
  prep_meta_k<<<1024, 256>>>(U,  U_R,     1024, 2048, 256, mu);
  prep_s1_k<<<4, 256>>>(v1, u2, v1_R, u2_R);

  cudaFuncSetAttribute(spgemm_k<0>, cudaFuncAttributeMaxDynamicSharedMemorySize, SMEMB);
  cudaFuncSetAttribute(spgemm_k<1>, cudaFuncAttributeMaxDynamicSharedMemorySize, SMEMB);

  // GEMM1: weights = sgn(V) (per branch), B = x' -> H' (pair-transformed, s1-scaled)
  dim3 g1(8, 64, 2);   // wtiles(1024/128) x btiles(8192/128) x branch
  spgemm_k<0><<<g1, 128, SMEMB>>>(cv, mv, xp, 4096,
                                  1024ull*2048, 64ull*128*16, 8192ull*4096,
                                  s1, hp, nullptr);
  // GEMM2: weights = sgn(Ucat)*u1, B = H' -> out + bias
  dim3 g2(32, 64, 1);  // wtiles(4096/128) x btiles
  spgemm_k<1><<<g2, 128, SMEMB>>>(cu, mu, hp, 2048,
                                  0, 0, 0,
                                  bias, nullptr, out);
}